// round 13
// baseline (speedup 1.0000x reference)
#include <cuda_runtime.h>

#define FULLM 0xFFFFFFFFu
#define NQ 10
#define NL 4

// 256 threads, 4 amps/thread. Amp index i (10 bits), wire q <-> bit (9-q).
// Layout A: i = (w<<7)|(k<<5)|lane ; w = tid>>5 (3b) -> wires 0,1,2 ;
//           k (2b) -> wires 3,4 (LOCAL) ; lane (5b) -> wires 5..9.
// Layout B: transpose T swaps i-bits (9,4)(8,3)(7,2).

__device__ __forceinline__ constexpr int sigma_c(int src) {  // CNOT-ring gather (GF(2)-linear)
  src ^= ((src >> 0) & 1) << 9;
  src ^= ((src >> 1) & 1) << 0;
  src ^= ((src >> 2) & 1) << 1;
  src ^= ((src >> 3) & 1) << 2;
  src ^= ((src >> 4) & 1) << 3;
  src ^= ((src >> 5) & 1) << 4;
  src ^= ((src >> 6) & 1) << 5;
  src ^= ((src >> 7) & 1) << 6;
  src ^= ((src >> 8) & 1) << 7;
  src ^= ((src >> 9) & 1) << 8;
  return src;
}
__device__ __forceinline__ constexpr int T_c(int x) {  // swap bits (9,4)(8,3)(7,2)
  return (x & ~0x39C) | ((x & 0x380) >> 5) | ((x & 0x1C) << 5);
}
__device__ __forceinline__ constexpr int swz(int j) { return j ^ ((j >> 5) & 31); }
__device__ __forceinline__ constexpr int SWK(int k) { return swz(k << 5); }
__device__ __forceinline__ constexpr int SGK(int k) { return swz(sigma_c(k << 5)); }

__global__ void __launch_bounds__(256)
hqh_kernel(const float* __restrict__ x,
           const float* __restrict__ params,
           float* __restrict__ out,
           int total4)
{
  __shared__ float bufA[1024], bufB[1024];
  __shared__ float pc[NL * NQ], ps[NL * NQ];
  __shared__ float r1[8][18];
  __shared__ float zbs[NQ], xbs[NQ];

  const int tid  = threadIdx.x;
  const int lane = tid & 31;
  const int w    = tid >> 5;

  if (tid < NL * NQ) {
    float s, c;
    __sincosf(0.5f * params[tid], &s, &c);
    pc[tid] = c; ps[tid] = s;
  }

  // prologue: both x float4 loads issued at t0 (L2-resident across replays)
  const int stride = gridDim.x * blockDim.x;     // 148*256 = 37888
  const int idx0 = blockIdx.x * blockDim.x + tid;
  float4 xv[2];
  #pragma unroll
  for (int j = 0; j < 2; j++) {
    const int idx = idx0 + j * stride;
    if (idx < total4 && (idx & 15) < 3) xv[j] = ((const float4*)x)[idx];
  }

  // hoisted GF(2)-linear address bases
  const int iA    = (w << 7) | lane;
  const int sA    = swz(iA);
  const int gT    = swz(T_c(iA));
  const int sigAi = sigma_c(iA);
  const int gS    = swz(sigAi);
  __syncthreads();

  float a[4];
  // ---- layer 0 closed form with its CNOT ring folded in ----
  {
    const int sk[4] = {0, 0x30, 0x60, 0x50};   // sigma(k<<5)
    #pragma unroll
    for (int k = 0; k < 4; k++) {
      const int si = sigAi ^ sk[k];
      float v = 1.f;
      #pragma unroll
      for (int q = 0; q < NQ; q++)
        v *= ((si >> (9 - q)) & 1) ? ps[q] : pc[q];
      a[k] = v;
    }
  }

  // ---- hoist epilogue trig off the critical tail (independent of circuit) ----
  float es[8], ec[8];
  #pragma unroll
  for (int j = 0; j < 2; j++) {
    const int idx = idx0 + j * stride;
    if (idx < total4 && (idx & 15) < 3) {
      __sincosf(xv[j].x, &es[j * 4 + 0], &ec[j * 4 + 0]);
      __sincosf(xv[j].y, &es[j * 4 + 1], &ec[j * 4 + 1]);
      __sincosf(xv[j].z, &es[j * 4 + 2], &ec[j * 4 + 2]);
      __sincosf(xv[j].w, &es[j * 4 + 3], &ec[j * 4 + 3]);
    }
  }

  #pragma unroll
  for (int l = 1; l < NL; l++) {
    const float* C = pc + l * NQ;
    const float* S = ps + l * NQ;
    const float C0=C[0],S0=S[0],C1=C[1],S1=S[1],C2=C[2],S2=S[2],C3=C[3],S3=S[3],C4=C[4],S4=S[4];
    const float C5=C[5],S5=S[5],C6=C[6],S6=S[6],C7=C[7],S7=S[7],C8=C[8],S8=S[8],C9=C[9],S9=S[9];

    // local wire 3 (k bit1)
    {
      float l0 = a[0], h0 = a[2], l1 = a[1], h1 = a[3];
      a[0] = C3 * l0 - S3 * h0;  a[2] = fmaf(S3, l0, C3 * h0);
      a[1] = C3 * l1 - S3 * h1;  a[3] = fmaf(S3, l1, C3 * h1);
    }
    // local wire 4 (k bit0)
    {
      float l0 = a[0], h0 = a[1], l1 = a[2], h1 = a[3];
      a[0] = C4 * l0 - S4 * h0;  a[1] = fmaf(S4, l0, C4 * h0);
      a[2] = C4 * l1 - S4 * h1;  a[3] = fmaf(S4, l1, C4 * h1);
    }
    // lane wires (5,6) fused rank-4 (masks 16,8)
    {
      const float sA5 = (lane & 16) ? S5 : -S5;
      const float sB6 = (lane & 8)  ? S6 : -S6;
      const float k00 = C5 * C6, k01 = C5 * sB6, k10 = sA5 * C6, k11 = sA5 * sB6;
      #pragma unroll
      for (int k = 0; k < 4; k++) {
        float vB  = __shfl_xor_sync(FULLM, a[k], 8);
        float vA  = __shfl_xor_sync(FULLM, a[k], 16);
        float vAB = __shfl_xor_sync(FULLM, a[k], 24);
        a[k] = fmaf(k00, a[k], fmaf(k01, vB, fmaf(k10, vA, k11 * vAB)));
      }
    }
    // lane wires (7,8,9) fused rank-8 (masks 4,2,1) — one dependent stage
    {
      const float s7 = (lane & 4) ? S7 : -S7;
      const float s8 = (lane & 2) ? S8 : -S8;
      const float s9 = (lane & 1) ? S9 : -S9;
      const float w00 = C7 * C8, w01 = C7 * s8, w10 = s7 * C8, w11 = s7 * s8;
      const float kk0 = w00 * C9, kk1 = w00 * s9;   // o=0,1
      const float kk2 = w01 * C9, kk3 = w01 * s9;   // o=2,3
      const float kk4 = w10 * C9, kk5 = w10 * s9;   // o=4,5
      const float kk6 = w11 * C9, kk7 = w11 * s9;   // o=6,7
      #pragma unroll
      for (int k = 0; k < 4; k++) {
        float v1 = __shfl_xor_sync(FULLM, a[k], 1);
        float v2 = __shfl_xor_sync(FULLM, a[k], 2);
        float v3 = __shfl_xor_sync(FULLM, a[k], 3);
        float v4 = __shfl_xor_sync(FULLM, a[k], 4);
        float v5 = __shfl_xor_sync(FULLM, a[k], 5);
        float v6 = __shfl_xor_sync(FULLM, a[k], 6);
        float v7 = __shfl_xor_sync(FULLM, a[k], 7);
        float t0 = fmaf(kk0, a[k], kk1 * v1);
        float t1 = fmaf(kk2, v2, kk3 * v3);
        float t2 = fmaf(kk4, v4, kk5 * v5);
        float t3 = fmaf(kk6, v6, kk7 * v7);
        a[k] = (t0 + t1) + (t2 + t3);
      }
    }
    // exchange A -> B (transpose)
    #pragma unroll
    for (int k = 0; k < 4; k++) bufA[sA ^ SWK(k)] = a[k];
    __syncthreads();
    #pragma unroll
    for (int k = 0; k < 4; k++) a[k] = bufA[gT ^ SWK(k)];
    // layout B: wires (0,1,2) fused rank-8 (lane masks 16,8,4) — one stage
    {
      const float s0 = (lane & 16) ? S0 : -S0;
      const float s1 = (lane & 8)  ? S1 : -S1;
      const float s2 = (lane & 4)  ? S2 : -S2;
      const float w00 = C0 * C1, w01 = C0 * s1, w10 = s0 * C1, w11 = s0 * s1;
      const float kk0 = w00 * C2, kk1 = w00 * s2;   // o=0,4
      const float kk2 = w01 * C2, kk3 = w01 * s2;   // o=8,12
      const float kk4 = w10 * C2, kk5 = w10 * s2;   // o=16,20
      const float kk6 = w11 * C2, kk7 = w11 * s2;   // o=24,28
      #pragma unroll
      for (int k = 0; k < 4; k++) {
        float v04 = __shfl_xor_sync(FULLM, a[k], 4);
        float v08 = __shfl_xor_sync(FULLM, a[k], 8);
        float v12 = __shfl_xor_sync(FULLM, a[k], 12);
        float v16 = __shfl_xor_sync(FULLM, a[k], 16);
        float v20 = __shfl_xor_sync(FULLM, a[k], 20);
        float v24 = __shfl_xor_sync(FULLM, a[k], 24);
        float v28 = __shfl_xor_sync(FULLM, a[k], 28);
        float t0 = fmaf(kk0, a[k], kk1 * v04);
        float t1 = fmaf(kk2, v08, kk3 * v12);
        float t2 = fmaf(kk4, v16, kk5 * v20);
        float t3 = fmaf(kk6, v24, kk7 * v28);
        a[k] = (t0 + t1) + (t2 + t3);
      }
    }
    // exchange B -> A with CNOT ring folded
    #pragma unroll
    for (int k = 0; k < 4; k++) bufB[gT ^ SWK(k)] = a[k];
    __syncthreads();
    #pragma unroll
    for (int k = 0; k < 4; k++) a[k] = bufB[gS ^ SGK(k)];
  }

  // ---- observables ----
  float p4[4];
  #pragma unroll
  for (int k = 0; k < 4; k++) p4[k] = a[k] * a[k];
  const float ptot = p4[0] + p4[1] + p4[2] + p4[3];

  float red[12];
  red[0] = (p4[0] + p4[1]) - (p4[2] + p4[3]);                 // z3
  red[1] = (p4[0] + p4[2]) - (p4[1] + p4[3]);                 // z4
  {
    float x0p = 0.f, x1p = 0.f, x2p = 0.f;
    #pragma unroll
    for (int k = 0; k < 4; k++) {
      const int b = gS ^ SGK(k);
      x0p = fmaf(a[k], bufB[b ^ 0x318], x0p);   // swz(sigma(0x200))
      x1p = fmaf(a[k], bufB[b ^ 0x18C], x1p);   // swz(sigma(0x100))
      x2p = fmaf(a[k], bufB[b ^ 0x0C6], x2p);   // swz(sigma(0x080))
    }
    red[2] = x0p; red[3] = x1p; red[4] = x2p;
  }
  red[5] = 2.f * (a[0] * a[2] + a[1] * a[3]);                 // x3
  red[6] = 2.f * (a[0] * a[1] + a[2] * a[3]);                 // x4
  #pragma unroll
  for (int q = 5; q < NQ; q++) {                              // x5..x9
    const int m = 1 << (9 - q);
    float s = 0.f;
    #pragma unroll
    for (int k = 0; k < 4; k++) s = fmaf(a[k], __shfl_xor_sync(FULLM, a[k], m), s);
    red[7 + q - 5] = s;
  }

  // Hadamard butterfly on ptot: v = warp total, d5..d9 diffs
  float v = ptot, d5, d6, d7, d8v, d9;
  { float p = __shfl_xor_sync(FULLM, v, 16); d5 = v - p; v += p; }
  { d5 += __shfl_xor_sync(FULLM, d5, 8);
    float p = __shfl_xor_sync(FULLM, v, 8);  d6 = v - p; v += p; }
  { d5 += __shfl_xor_sync(FULLM, d5, 4); d6 += __shfl_xor_sync(FULLM, d6, 4);
    float p = __shfl_xor_sync(FULLM, v, 4);  d7 = v - p; v += p; }
  { d5 += __shfl_xor_sync(FULLM, d5, 2); d6 += __shfl_xor_sync(FULLM, d6, 2);
    d7 += __shfl_xor_sync(FULLM, d7, 2);
    float p = __shfl_xor_sync(FULLM, v, 2);  d8v = v - p; v += p; }
  { d5 += __shfl_xor_sync(FULLM, d5, 1); d6 += __shfl_xor_sync(FULLM, d6, 1);
    d7 += __shfl_xor_sync(FULLM, d7, 1); d8v += __shfl_xor_sync(FULLM, d8v, 1);
    float p = __shfl_xor_sync(FULLM, v, 1);  d9 = v - p; v += p; }
  #pragma unroll
  for (int j = 0; j < 12; j++) {
    #pragma unroll
    for (int m = 16; m >= 1; m >>= 1) red[j] += __shfl_xor_sync(FULLM, red[j], m);
  }

  if (lane == 0) {
    r1[w][0] = v;
    r1[w][1] = d5; r1[w][2] = d6; r1[w][3] = d7; r1[w][4] = d8v; r1[w][5] = d9;
    r1[w][6] = red[0]; r1[w][7] = red[1];
    #pragma unroll
    for (int j = 0; j < 10; j++) r1[w][8 + j] = red[2 + j];
  }
  __syncthreads();
  if (tid < 20) {
    float s = 0.f;
    if (tid < 3) {           // z0,z1,z2: sign = warp bit (2-tid)
      const int sb = 1 << (2 - tid);
      #pragma unroll
      for (int i = 0; i < 8; i++) s += (i & sb) ? -r1[i][0] : r1[i][0];
      zbs[tid] = s;
    } else if (tid < 5) {    // z3,z4
      #pragma unroll
      for (int i = 0; i < 8; i++) s += r1[i][tid + 3];
      zbs[tid] = s;
    } else if (tid < 10) {   // z5..z9
      #pragma unroll
      for (int i = 0; i < 8; i++) s += r1[i][tid - 4];
      zbs[tid] = s;
    } else {                 // x0..x9
      #pragma unroll
      for (int i = 0; i < 8; i++) s += r1[i][tid - 2];
      xbs[tid - 10] = s;
    }
  }
  __syncthreads();

  // ---- epilogue: trig precomputed; just FMA + store ----
  #pragma unroll
  for (int j = 0; j < 2; j++) {
    const int idx = idx0 + j * stride;
    if (idx < total4) {
      const int c4 = idx & 15;
      float4 o = make_float4(0.f, 0.f, 0.f, 0.f);
      if (c4 < 3) {
        const int q0 = c4 * 4;
        o.x = ec[j * 4 + 0] * zbs[q0]     - es[j * 4 + 0] * xbs[q0];
        o.y = ec[j * 4 + 1] * zbs[q0 + 1] - es[j * 4 + 1] * xbs[q0 + 1];
        if (c4 < 2) {
          o.z = ec[j * 4 + 2] * zbs[q0 + 2] - es[j * 4 + 2] * xbs[q0 + 2];
          o.w = ec[j * 4 + 3] * zbs[q0 + 3] - es[j * 4 + 3] * xbs[q0 + 3];
        }
      }
      ((float4*)out)[idx] = o;
    }
  }
}

extern "C" void kernel_launch(void* const* d_in, const int* in_sizes, int n_in,
                              void* d_out, int out_size) {
  const float* x = (const float*)d_in[0];
  const float* params = (const float*)d_in[1];
  if (n_in >= 2 && in_sizes[0] == NL * NQ) {   // robust to input ordering
    params = (const float*)d_in[0];
    x = (const float*)d_in[1];
  }
  const int total4 = out_size / 4;   // output float4 count
  // 148 blocks (1/SM), 2 float4 per thread covers up to 75776 >= 65536
  hqh_kernel<<<148, 256>>>(x, params, (float*)d_out, total4);
}

// round 14
// speedup vs baseline: 1.0608x; 1.0608x over previous
#include <cuda_runtime.h>

#define FULLM 0xFFFFFFFFu
#define NQ 10
#define NL 4

// 256 threads, 4 amps/thread. Amp index i (10 bits), wire q <-> bit (9-q).
// Layout A: i = (w<<7)|(k<<5)|lane ; w = tid>>5 (3b) -> wires 0,1,2 ;
//           k (2b) -> wires 3,4 (LOCAL) ; lane (5b) -> wires 5..9.
// Layout B: transpose T swaps i-bits (9,4)(8,3)(7,2).

__device__ __forceinline__ constexpr int sigma_c(int src) {  // CNOT-ring gather (GF(2)-linear)
  src ^= ((src >> 0) & 1) << 9;
  src ^= ((src >> 1) & 1) << 0;
  src ^= ((src >> 2) & 1) << 1;
  src ^= ((src >> 3) & 1) << 2;
  src ^= ((src >> 4) & 1) << 3;
  src ^= ((src >> 5) & 1) << 4;
  src ^= ((src >> 6) & 1) << 5;
  src ^= ((src >> 7) & 1) << 6;
  src ^= ((src >> 8) & 1) << 7;
  src ^= ((src >> 9) & 1) << 8;
  return src;
}
__device__ __forceinline__ constexpr int T_c(int x) {  // swap bits (9,4)(8,3)(7,2)
  return (x & ~0x39C) | ((x & 0x380) >> 5) | ((x & 0x1C) << 5);
}
__device__ __forceinline__ constexpr int swz(int j) { return j ^ ((j >> 5) & 31); }
__device__ __forceinline__ constexpr int SWK(int k) { return swz(k << 5); }
__device__ __forceinline__ constexpr int SGK(int k) { return swz(sigma_c(k << 5)); }

__global__ void __launch_bounds__(256)
hqh_kernel(const float* __restrict__ x,
           const float* __restrict__ params,
           float* __restrict__ out,
           int total4)
{
  __shared__ float bufA[1024], bufB[1024];
  __shared__ float pc[NL * NQ], ps[NL * NQ];
  __shared__ float r1[8][18];
  __shared__ float zbs[NQ], xbs[NQ];

  const int tid  = threadIdx.x;
  const int lane = tid & 31;
  const int w    = tid >> 5;

  if (tid < NL * NQ) {
    float s, c;
    __sincosf(0.5f * params[tid], &s, &c);
    pc[tid] = c; ps[tid] = s;
  }

  // prologue: both x float4 loads issued at t0 (L2-resident across replays)
  const int stride = gridDim.x * blockDim.x;     // 148*256 = 37888
  const int idx0 = blockIdx.x * blockDim.x + tid;
  float4 xv[2];
  #pragma unroll
  for (int j = 0; j < 2; j++) {
    const int idx = idx0 + j * stride;
    if (idx < total4 && (idx & 15) < 3) xv[j] = ((const float4*)x)[idx];
  }

  // hoisted GF(2)-linear address bases
  const int iA    = (w << 7) | lane;
  const int sA    = swz(iA);
  const int gT    = swz(T_c(iA));
  const int sigAi = sigma_c(iA);
  const int gS    = swz(sigAi);
  __syncthreads();

  float a[4];
  // ---- layer 0 closed form with its CNOT ring folded in ----
  {
    const int sk[4] = {0, 0x30, 0x60, 0x50};   // sigma(k<<5)
    #pragma unroll
    for (int k = 0; k < 4; k++) {
      const int si = sigAi ^ sk[k];
      float v = 1.f;
      #pragma unroll
      for (int q = 0; q < NQ; q++)
        v *= ((si >> (9 - q)) & 1) ? ps[q] : pc[q];
      a[k] = v;
    }
  }

  // ---- hoist epilogue trig off the critical tail (independent of circuit) ----
  float es[8], ec[8];
  #pragma unroll
  for (int j = 0; j < 2; j++) {
    const int idx = idx0 + j * stride;
    if (idx < total4 && (idx & 15) < 3) {
      __sincosf(xv[j].x, &es[j * 4 + 0], &ec[j * 4 + 0]);
      __sincosf(xv[j].y, &es[j * 4 + 1], &ec[j * 4 + 1]);
      __sincosf(xv[j].z, &es[j * 4 + 2], &ec[j * 4 + 2]);
      __sincosf(xv[j].w, &es[j * 4 + 3], &ec[j * 4 + 3]);
    }
  }

  #pragma unroll
  for (int l = 1; l < NL; l++) {
    const float* C = pc + l * NQ;
    const float* S = ps + l * NQ;
    const float C0=C[0],S0=S[0],C1=C[1],S1=S[1],C2=C[2],S2=S[2],C3=C[3],S3=S[3],C4=C[4],S4=S[4];
    const float C5=C[5],S5=S[5],C6=C[6],S6=S[6],C7=C[7],S7=S[7],C8=C[8],S8=S[8],C9=C[9],S9=S[9];

    // local wire 3 (k bit1)
    {
      float l0 = a[0], h0 = a[2], l1 = a[1], h1 = a[3];
      a[0] = C3 * l0 - S3 * h0;  a[2] = fmaf(S3, l0, C3 * h0);
      a[1] = C3 * l1 - S3 * h1;  a[3] = fmaf(S3, l1, C3 * h1);
    }
    // local wire 4 (k bit0)
    {
      float l0 = a[0], h0 = a[1], l1 = a[2], h1 = a[3];
      a[0] = C4 * l0 - S4 * h0;  a[1] = fmaf(S4, l0, C4 * h0);
      a[2] = C4 * l1 - S4 * h1;  a[3] = fmaf(S4, l1, C4 * h1);
    }
    // lane wires (5,6) fused rank-4 (masks 16,8)
    {
      const float sA5 = (lane & 16) ? S5 : -S5;
      const float sB6 = (lane & 8)  ? S6 : -S6;
      const float k00 = C5 * C6, k01 = C5 * sB6, k10 = sA5 * C6, k11 = sA5 * sB6;
      #pragma unroll
      for (int k = 0; k < 4; k++) {
        float vB  = __shfl_xor_sync(FULLM, a[k], 8);
        float vA  = __shfl_xor_sync(FULLM, a[k], 16);
        float vAB = __shfl_xor_sync(FULLM, a[k], 24);
        a[k] = fmaf(k00, a[k], fmaf(k01, vB, fmaf(k10, vA, k11 * vAB)));
      }
    }
    // lane wires (7,8) fused rank-4 (masks 4,2)
    {
      const float sA7 = (lane & 4) ? S7 : -S7;
      const float sB8 = (lane & 2) ? S8 : -S8;
      const float k00 = C7 * C8, k01 = C7 * sB8, k10 = sA7 * C8, k11 = sA7 * sB8;
      #pragma unroll
      for (int k = 0; k < 4; k++) {
        float vB  = __shfl_xor_sync(FULLM, a[k], 2);
        float vA  = __shfl_xor_sync(FULLM, a[k], 4);
        float vAB = __shfl_xor_sync(FULLM, a[k], 6);
        a[k] = fmaf(k00, a[k], fmaf(k01, vB, fmaf(k10, vA, k11 * vAB)));
      }
    }
    // lane wire 9 (mask 1)
    {
      const float se = (lane & 1) ? S9 : -S9;
      #pragma unroll
      for (int k = 0; k < 4; k++) {
        float p = __shfl_xor_sync(FULLM, a[k], 1);
        a[k] = fmaf(C9, a[k], se * p);
      }
    }
    // exchange A -> B (transpose)
    #pragma unroll
    for (int k = 0; k < 4; k++) bufA[sA ^ SWK(k)] = a[k];
    __syncthreads();
    #pragma unroll
    for (int k = 0; k < 4; k++) a[k] = bufA[gT ^ SWK(k)];
    // layout B: wires (0,1) fused rank-4 (masks 16,8)
    {
      const float sA0 = (lane & 16) ? S0 : -S0;
      const float sB1 = (lane & 8)  ? S1 : -S1;
      const float k00 = C0 * C1, k01 = C0 * sB1, k10 = sA0 * C1, k11 = sA0 * sB1;
      #pragma unroll
      for (int k = 0; k < 4; k++) {
        float vB  = __shfl_xor_sync(FULLM, a[k], 8);
        float vA  = __shfl_xor_sync(FULLM, a[k], 16);
        float vAB = __shfl_xor_sync(FULLM, a[k], 24);
        a[k] = fmaf(k00, a[k], fmaf(k01, vB, fmaf(k10, vA, k11 * vAB)));
      }
    }
    // layout B: wire 2 (mask 4)
    {
      const float se = (lane & 4) ? S2 : -S2;
      #pragma unroll
      for (int k = 0; k < 4; k++) {
        float p = __shfl_xor_sync(FULLM, a[k], 4);
        a[k] = fmaf(C2, a[k], se * p);
      }
    }
    // exchange B -> A with CNOT ring folded
    #pragma unroll
    for (int k = 0; k < 4; k++) bufB[gT ^ SWK(k)] = a[k];
    __syncthreads();
    #pragma unroll
    for (int k = 0; k < 4; k++) a[k] = bufB[gS ^ SGK(k)];
  }

  // ---- observables ----
  float p4[4];
  #pragma unroll
  for (int k = 0; k < 4; k++) p4[k] = a[k] * a[k];
  const float ptot = p4[0] + p4[1] + p4[2] + p4[3];

  float red[12];
  red[0] = (p4[0] + p4[1]) - (p4[2] + p4[3]);                 // z3
  red[1] = (p4[0] + p4[2]) - (p4[1] + p4[3]);                 // z4
  {
    float x0p = 0.f, x1p = 0.f, x2p = 0.f;
    #pragma unroll
    for (int k = 0; k < 4; k++) {
      const int b = gS ^ SGK(k);
      x0p = fmaf(a[k], bufB[b ^ 0x318], x0p);   // swz(sigma(0x200))
      x1p = fmaf(a[k], bufB[b ^ 0x18C], x1p);   // swz(sigma(0x100))
      x2p = fmaf(a[k], bufB[b ^ 0x0C6], x2p);   // swz(sigma(0x080))
    }
    red[2] = x0p; red[3] = x1p; red[4] = x2p;
  }
  red[5] = 2.f * (a[0] * a[2] + a[1] * a[3]);                 // x3
  red[6] = 2.f * (a[0] * a[1] + a[2] * a[3]);                 // x4
  #pragma unroll
  for (int q = 5; q < NQ; q++) {                              // x5..x9
    const int m = 1 << (9 - q);
    float s = 0.f;
    #pragma unroll
    for (int k = 0; k < 4; k++) s = fmaf(a[k], __shfl_xor_sync(FULLM, a[k], m), s);
    red[7 + q - 5] = s;
  }

  // Hadamard butterfly on ptot: v = warp total, d5..d9 diffs
  float v = ptot, d5, d6, d7, d8v, d9;
  { float p = __shfl_xor_sync(FULLM, v, 16); d5 = v - p; v += p; }
  { d5 += __shfl_xor_sync(FULLM, d5, 8);
    float p = __shfl_xor_sync(FULLM, v, 8);  d6 = v - p; v += p; }
  { d5 += __shfl_xor_sync(FULLM, d5, 4); d6 += __shfl_xor_sync(FULLM, d6, 4);
    float p = __shfl_xor_sync(FULLM, v, 4);  d7 = v - p; v += p; }
  { d5 += __shfl_xor_sync(FULLM, d5, 2); d6 += __shfl_xor_sync(FULLM, d6, 2);
    d7 += __shfl_xor_sync(FULLM, d7, 2);
    float p = __shfl_xor_sync(FULLM, v, 2);  d8v = v - p; v += p; }
  { d5 += __shfl_xor_sync(FULLM, d5, 1); d6 += __shfl_xor_sync(FULLM, d6, 1);
    d7 += __shfl_xor_sync(FULLM, d7, 1); d8v += __shfl_xor_sync(FULLM, d8v, 1);
    float p = __shfl_xor_sync(FULLM, v, 1);  d9 = v - p; v += p; }
  #pragma unroll
  for (int j = 0; j < 12; j++) {
    #pragma unroll
    for (int m = 16; m >= 1; m >>= 1) red[j] += __shfl_xor_sync(FULLM, red[j], m);
  }

  if (lane == 0) {
    r1[w][0] = v;
    r1[w][1] = d5; r1[w][2] = d6; r1[w][3] = d7; r1[w][4] = d8v; r1[w][5] = d9;
    r1[w][6] = red[0]; r1[w][7] = red[1];
    #pragma unroll
    for (int j = 0; j < 10; j++) r1[w][8 + j] = red[2 + j];
  }
  __syncthreads();
  if (tid < 20) {
    float s = 0.f;
    if (tid < 3) {           // z0,z1,z2: sign = warp bit (2-tid)
      const int sb = 1 << (2 - tid);
      #pragma unroll
      for (int i = 0; i < 8; i++) s += (i & sb) ? -r1[i][0] : r1[i][0];
      zbs[tid] = s;
    } else if (tid < 5) {    // z3,z4
      #pragma unroll
      for (int i = 0; i < 8; i++) s += r1[i][tid + 3];
      zbs[tid] = s;
    } else if (tid < 10) {   // z5..z9
      #pragma unroll
      for (int i = 0; i < 8; i++) s += r1[i][tid - 4];
      zbs[tid] = s;
    } else {                 // x0..x9
      #pragma unroll
      for (int i = 0; i < 8; i++) s += r1[i][tid - 2];
      xbs[tid - 10] = s;
    }
  }
  __syncthreads();

  // ---- epilogue: trig precomputed; just FMA + store ----
  #pragma unroll
  for (int j = 0; j < 2; j++) {
    const int idx = idx0 + j * stride;
    if (idx < total4) {
      const int c4 = idx & 15;
      float4 o = make_float4(0.f, 0.f, 0.f, 0.f);
      if (c4 < 3) {
        const int q0 = c4 * 4;
        o.x = ec[j * 4 + 0] * zbs[q0]     - es[j * 4 + 0] * xbs[q0];
        o.y = ec[j * 4 + 1] * zbs[q0 + 1] - es[j * 4 + 1] * xbs[q0 + 1];
        if (c4 < 2) {
          o.z = ec[j * 4 + 2] * zbs[q0 + 2] - es[j * 4 + 2] * xbs[q0 + 2];
          o.w = ec[j * 4 + 3] * zbs[q0 + 3] - es[j * 4 + 3] * xbs[q0 + 3];
        }
      }
      ((float4*)out)[idx] = o;
    }
  }
}

extern "C" void kernel_launch(void* const* d_in, const int* in_sizes, int n_in,
                              void* d_out, int out_size) {
  const float* x = (const float*)d_in[0];
  const float* params = (const float*)d_in[1];
  if (n_in >= 2 && in_sizes[0] == NL * NQ) {   // robust to input ordering
    params = (const float*)d_in[0];
    x = (const float*)d_in[1];
  }
  const int total4 = out_size / 4;   // output float4 count
  // 148 blocks (1/SM), 2 float4 per thread covers up to 75776 >= 65536
  hqh_kernel<<<148, 256>>>(x, params, (float*)d_out, total4);
}